// round 1
// baseline (speedup 1.0000x reference)
#include <cuda_runtime.h>
#include <math.h>

#define D_MODEL   1024
#define NUM_HEADS 16
#define D_HEAD    64
#define BATCH     4
#define SEQ       2048
#define MROWS     (BATCH * SEQ)   /* 8192 */
#define ATT_SCALE 0.125f          /* 1/sqrt(64) */

/* ------------------------------------------------------------------ */
/* Scratch (device globals: allocation-free per harness rules)         */
/* ------------------------------------------------------------------ */
__device__ float g_Q[(size_t)MROWS * D_MODEL];
__device__ float g_K[(size_t)MROWS * D_MODEL];
__device__ float g_V[(size_t)MROWS * D_MODEL];
__device__ float g_O[(size_t)MROWS * D_MODEL];

/* ------------------------------------------------------------------ */
/* GEMM: C[m][n] = sum_k A[m][k] * W[n][k] + bias[n]                   */
/* A: [M,K] row-major, W: [N,K] row-major (torch Linear weight)        */
/* 128x128 tile, BK=8, 256 threads, 8x8 microtile                      */
/* ------------------------------------------------------------------ */
__global__ __launch_bounds__(256)
void sgemm_bias_kernel(const float* __restrict__ A,
                       const float* __restrict__ W,
                       const float* __restrict__ bias,
                       float* __restrict__ C,
                       int M, int N, int K)
{
    __shared__ float As[8][128];
    __shared__ float Bs[8][128];

    const int tid = threadIdx.x;
    const int m0  = blockIdx.y * 128;
    const int n0  = blockIdx.x * 128;
    const int ty  = tid >> 4;
    const int tx  = tid & 15;
    const int r0  = ty * 8;
    const int c0  = tx * 8;

    float acc[8][8];
#pragma unroll
    for (int i = 0; i < 8; i++)
#pragma unroll
        for (int j = 0; j < 8; j++) acc[i][j] = 0.0f;

    const int arow = tid >> 1;        /* 0..127 */
    const int acol = (tid & 1) * 4;   /* 0 or 4 */
    const float* Aptr = A + (size_t)(m0 + arow) * K + acol;
    const float* Wptr = W + (size_t)(n0 + arow) * K + acol;

    for (int k0 = 0; k0 < K; k0 += 8) {
        const float4 av = *(const float4*)(Aptr + k0);
        const float4 wv = *(const float4*)(Wptr + k0);

        __syncthreads();
        As[acol + 0][arow] = av.x;
        As[acol + 1][arow] = av.y;
        As[acol + 2][arow] = av.z;
        As[acol + 3][arow] = av.w;
        Bs[acol + 0][arow] = wv.x;
        Bs[acol + 1][arow] = wv.y;
        Bs[acol + 2][arow] = wv.z;
        Bs[acol + 3][arow] = wv.w;
        __syncthreads();

#pragma unroll
        for (int k = 0; k < 8; k++) {
            float af[8], bf[8];
            *(float4*)(af)     = *(const float4*)&As[k][r0];
            *(float4*)(af + 4) = *(const float4*)&As[k][r0 + 4];
            *(float4*)(bf)     = *(const float4*)&Bs[k][c0];
            *(float4*)(bf + 4) = *(const float4*)&Bs[k][c0 + 4];
#pragma unroll
            for (int i = 0; i < 8; i++)
#pragma unroll
                for (int j = 0; j < 8; j++)
                    acc[i][j] += af[i] * bf[j];
        }
    }

    /* epilogue: add bias, vectorized store */
    float bf[8];
    *(float4*)(bf)     = *(const float4*)(bias + n0 + c0);
    *(float4*)(bf + 4) = *(const float4*)(bias + n0 + c0 + 4);

#pragma unroll
    for (int i = 0; i < 8; i++) {
        float* crow = C + (size_t)(m0 + r0 + i) * N + n0 + c0;
        float4 o0, o1;
        o0.x = acc[i][0] + bf[0]; o0.y = acc[i][1] + bf[1];
        o0.z = acc[i][2] + bf[2]; o0.w = acc[i][3] + bf[3];
        o1.x = acc[i][4] + bf[4]; o1.y = acc[i][5] + bf[5];
        o1.z = acc[i][6] + bf[6]; o1.w = acc[i][7] + bf[7];
        *(float4*)(crow)     = o0;
        *(float4*)(crow + 4) = o1;
    }
}

/* ------------------------------------------------------------------ */
/* Flash attention (fp32, online softmax)                              */
/* block = 128 query rows of one (b,h); key tiles of 64                */
/* threads: 256 -> 8x4 microtile (8 q-rows, 4 head-dims)               */
/* smem rows padded to 68 floats (bank-safe, float4-aligned)           */
/* ------------------------------------------------------------------ */
#define PAD 68
#define ATT_SMEM_BYTES ((128 * PAD + 64 * PAD + 64 * PAD + 128 * PAD) * 4) /* 104448 */

__global__ __launch_bounds__(256)
void attn_kernel()
{
    extern __shared__ float sm[];
    float* Qs = sm;                      /* 128 x PAD */
    float* Ks = Qs + 128 * PAD;          /*  64 x PAD */
    float* Vs = Ks + 64 * PAD;           /*  64 x PAD */
    float* Ps = Vs + 64 * PAD;           /* 128 x PAD */

    const int tid = threadIdx.x;
    const int bh  = blockIdx.y;
    const int b   = bh >> 4;
    const int h   = bh & 15;
    const int q0  = blockIdx.x * 128;
    const int ty  = tid >> 4;
    const int tx  = tid & 15;
    const int r0  = ty * 8;   /* query rows   */
    const int c0  = tx * 4;   /* key cols / head dims */

    const size_t base = (size_t)b * SEQ * D_MODEL + (size_t)h * D_HEAD;
    const float* Qg = g_Q + base;
    const float* Kg = g_K + base;
    const float* Vg = g_V + base;

    /* load Q tile: 128 x 64 floats = 2048 float4, 8 per thread */
#pragma unroll
    for (int i = 0; i < 8; i++) {
        int f4  = tid + i * 256;
        int row = f4 >> 4;
        int c4  = (f4 & 15) * 4;
        *(float4*)&Qs[row * PAD + c4] =
            *(const float4*)(Qg + (size_t)(q0 + row) * D_MODEL + c4);
    }

    float m_i[8], l_i[8], acc[8][4];
#pragma unroll
    for (int i = 0; i < 8; i++) {
        m_i[i] = -1e30f;
        l_i[i] = 0.0f;
#pragma unroll
        for (int j = 0; j < 4; j++) acc[i][j] = 0.0f;
    }

    for (int kt = 0; kt < SEQ; kt += 64) {
        __syncthreads();
        /* load K,V tiles: 64 x 64 = 1024 float4 each, 4 per thread */
#pragma unroll
        for (int i = 0; i < 4; i++) {
            int f4  = tid + i * 256;
            int row = f4 >> 4;
            int c4  = (f4 & 15) * 4;
            *(float4*)&Ks[row * PAD + c4] =
                *(const float4*)(Kg + (size_t)(kt + row) * D_MODEL + c4);
            *(float4*)&Vs[row * PAD + c4] =
                *(const float4*)(Vg + (size_t)(kt + row) * D_MODEL + c4);
        }
        __syncthreads();

        /* scores: sc[i][j] = Q[r0+i] . K[c0+j] */
        float sc[8][4];
#pragma unroll
        for (int i = 0; i < 8; i++)
#pragma unroll
            for (int j = 0; j < 4; j++) sc[i][j] = 0.0f;

        for (int k4 = 0; k4 < 64; k4 += 4) {
            float4 kv[4];
#pragma unroll
            for (int j = 0; j < 4; j++)
                kv[j] = *(const float4*)&Ks[(c0 + j) * PAD + k4];
#pragma unroll
            for (int i = 0; i < 8; i++) {
                float4 qv = *(const float4*)&Qs[(r0 + i) * PAD + k4];
#pragma unroll
                for (int j = 0; j < 4; j++) {
                    sc[i][j] += qv.x * kv[j].x;
                    sc[i][j] += qv.y * kv[j].y;
                    sc[i][j] += qv.z * kv[j].z;
                    sc[i][j] += qv.w * kv[j].w;
                }
            }
        }

        /* online softmax (rows spread over 16-lane tx groups) */
#pragma unroll
        for (int i = 0; i < 8; i++) {
            float mt = -1e30f;
#pragma unroll
            for (int j = 0; j < 4; j++) {
                sc[i][j] *= ATT_SCALE;
                mt = fmaxf(mt, sc[i][j]);
            }
#pragma unroll
            for (int off = 8; off > 0; off >>= 1)
                mt = fmaxf(mt, __shfl_xor_sync(0xffffffffu, mt, off));
            float mnew = fmaxf(m_i[i], mt);
            float corr = __expf(m_i[i] - mnew);
            float rs = 0.0f;
#pragma unroll
            for (int j = 0; j < 4; j++) {
                float p = __expf(sc[i][j] - mnew);
                Ps[(r0 + i) * PAD + c0 + j] = p;
                rs += p;
            }
#pragma unroll
            for (int off = 8; off > 0; off >>= 1)
                rs += __shfl_xor_sync(0xffffffffu, rs, off);
            l_i[i] = l_i[i] * corr + rs;
            m_i[i] = mnew;
#pragma unroll
            for (int j = 0; j < 4; j++) acc[i][j] *= corr;
        }
        __syncwarp();   /* Ps rows for this thread were written by its own warp */

        /* acc += P . V */
        for (int kk4 = 0; kk4 < 64; kk4 += 4) {
            float4 vv[4];
#pragma unroll
            for (int q = 0; q < 4; q++)
                vv[q] = *(const float4*)&Vs[(kk4 + q) * PAD + c0];
#pragma unroll
            for (int i = 0; i < 8; i++) {
                float4 pv = *(const float4*)&Ps[(r0 + i) * PAD + kk4];
                acc[i][0] += pv.x * vv[0].x + pv.y * vv[1].x + pv.z * vv[2].x + pv.w * vv[3].x;
                acc[i][1] += pv.x * vv[0].y + pv.y * vv[1].y + pv.z * vv[2].y + pv.w * vv[3].y;
                acc[i][2] += pv.x * vv[0].z + pv.y * vv[1].z + pv.z * vv[2].z + pv.w * vv[3].z;
                acc[i][3] += pv.x * vv[0].w + pv.y * vv[1].w + pv.z * vv[2].w + pv.w * vv[3].w;
            }
        }
    }

    /* epilogue: normalize, write to g_O in [B, S, H*Dh] layout */
    float* Og = g_O + base;
#pragma unroll
    for (int i = 0; i < 8; i++) {
        float inv = 1.0f / l_i[i];
        float4 o;
        o.x = acc[i][0] * inv;
        o.y = acc[i][1] * inv;
        o.z = acc[i][2] * inv;
        o.w = acc[i][3] * inv;
        *(float4*)(Og + (size_t)(q0 + r0 + i) * D_MODEL + c0) = o;
    }
}

/* ------------------------------------------------------------------ */
/* launch                                                              */
/* ------------------------------------------------------------------ */
extern "C" void kernel_launch(void* const* d_in, const int* in_sizes, int n_in,
                              void* d_out, int out_size)
{
    const float* x  = (const float*)d_in[0];
    const float* Wq = (const float*)d_in[1];
    const float* bq = (const float*)d_in[2];
    const float* Wk = (const float*)d_in[3];
    const float* bk = (const float*)d_in[4];
    const float* Wv = (const float*)d_in[5];
    const float* bv = (const float*)d_in[6];
    const float* Wo = (const float*)d_in[7];
    const float* bo = (const float*)d_in[8];
    float* out = (float*)d_out;

    float *q, *k, *v, *o;
    cudaGetSymbolAddress((void**)&q, g_Q);
    cudaGetSymbolAddress((void**)&k, g_K);
    cudaGetSymbolAddress((void**)&v, g_V);
    cudaGetSymbolAddress((void**)&o, g_O);

    cudaFuncSetAttribute(attn_kernel,
                         cudaFuncAttributeMaxDynamicSharedMemorySize,
                         ATT_SMEM_BYTES);

    dim3 gemm_grid(D_MODEL / 128, MROWS / 128);   /* (8, 64) */
    sgemm_bias_kernel<<<gemm_grid, 256>>>(x, Wq, bq, q, MROWS, D_MODEL, D_MODEL);
    sgemm_bias_kernel<<<gemm_grid, 256>>>(x, Wk, bk, k, MROWS, D_MODEL, D_MODEL);
    sgemm_bias_kernel<<<gemm_grid, 256>>>(x, Wv, bv, v, MROWS, D_MODEL, D_MODEL);

    dim3 attn_grid(SEQ / 128, BATCH * NUM_HEADS);  /* (16, 64) */
    attn_kernel<<<attn_grid, 256, ATT_SMEM_BYTES>>>();

    sgemm_bias_kernel<<<gemm_grid, 256>>>(o, Wo, bo, out, MROWS, D_MODEL, D_MODEL);
}

// round 3
// speedup vs baseline: 1.4039x; 1.4039x over previous
#include <cuda_runtime.h>
#include <cuda_bf16.h>
#include <stdint.h>
#include <math.h>

#define D_MODEL   1024
#define NUM_HEADS 16
#define D_HEAD    64
#define BATCH     4
#define SEQ       2048
#define MROWS     (BATCH * SEQ)   /* 8192 */
#define ATT_SCALE 0.125f

/* ================================================================== */
/* helpers                                                             */
/* ================================================================== */
__device__ __forceinline__ uint32_t smem_u32(const void* p) {
    uint32_t a;
    asm("{ .reg .u64 t; cvta.to.shared.u64 t, %1; cvt.u32.u64 %0, t; }"
        : "=r"(a) : "l"(p));
    return a;
}

#define CP_ASYNC16(saddr, gptr) \
    asm volatile("cp.async.cg.shared.global [%0], [%1], 16;" \
        :: "r"(saddr), "l"(gptr) : "memory")
#define CP_COMMIT() asm volatile("cp.async.commit_group;" ::: "memory")
#define CP_WAIT(n)  asm volatile("cp.async.wait_group %0;" :: "n"(n) : "memory")

#define LDM4(r, a) \
    asm volatile("ldmatrix.sync.aligned.m8n8.x4.shared.b16 {%0,%1,%2,%3}, [%4];" \
        : "=r"((r)[0]), "=r"((r)[1]), "=r"((r)[2]), "=r"((r)[3]) : "r"(a))

#define MMA16816(d, a, b0, b1) \
    asm volatile("mma.sync.aligned.m16n8k16.row.col.f32.bf16.bf16.f32 " \
        "{%0,%1,%2,%3},{%4,%5,%6,%7},{%8,%9},{%0,%1,%2,%3};" \
        : "+f"((d)[0]), "+f"((d)[1]), "+f"((d)[2]), "+f"((d)[3]) \
        : "r"((a)[0]), "r"((a)[1]), "r"((a)[2]), "r"((a)[3]), \
          "r"(b0), "r"(b1))

/* ================================================================== */
/* Scratch                                                             */
/* ================================================================== */
__device__ float g_Q[(size_t)MROWS * D_MODEL];
__device__ float g_K[(size_t)MROWS * D_MODEL];
__device__ float g_V[(size_t)MROWS * D_MODEL];
__device__ float g_O[(size_t)MROWS * D_MODEL];
__device__ __nv_bfloat16 g_Xhi[(size_t)MROWS * D_MODEL];  /* reused for O */
__device__ __nv_bfloat16 g_Xlo[(size_t)MROWS * D_MODEL];
__device__ __nv_bfloat16 g_Whi[(size_t)4 * D_MODEL * D_MODEL];
__device__ __nv_bfloat16 g_Wlo[(size_t)4 * D_MODEL * D_MODEL];

/* ================================================================== */
/* fp32 -> bf16 hi/lo split                                            */
/* ================================================================== */
__global__ __launch_bounds__(256)
void cvt_split_kernel(const float4* __restrict__ in,
                      __nv_bfloat162* __restrict__ hi,
                      __nv_bfloat162* __restrict__ lo, int n4)
{
    int i = blockIdx.x * 256 + threadIdx.x;
    if (i >= n4) return;
    float4 v = in[i];
    __nv_bfloat16 hx = __float2bfloat16_rn(v.x);
    __nv_bfloat16 hy = __float2bfloat16_rn(v.y);
    __nv_bfloat16 hz = __float2bfloat16_rn(v.z);
    __nv_bfloat16 hw = __float2bfloat16_rn(v.w);
    __nv_bfloat162 h0; h0.x = hx; h0.y = hy;
    __nv_bfloat162 h1; h1.x = hz; h1.y = hw;
    __nv_bfloat162 l0, l1;
    l0.x = __float2bfloat16_rn(v.x - __bfloat162float(hx));
    l0.y = __float2bfloat16_rn(v.y - __bfloat162float(hy));
    l1.x = __float2bfloat16_rn(v.z - __bfloat162float(hz));
    l1.y = __float2bfloat16_rn(v.w - __bfloat162float(hw));
    hi[i * 2] = h0; hi[i * 2 + 1] = h1;
    lo[i * 2] = l0; lo[i * 2 + 1] = l1;
}

/* ================================================================== */
/* bf16 split GEMM via mma.sync (HMMA)                                 */
/* C[m][n] = sum_k A[m][k]*W[n][k] + bias[n], fp32 accum               */
/* CTA 128x128, BK=32, 8 warps -> 64x32 warp tiles, double-buffered    */
/* smem row stride 80B (64B data + 16B pad) -> conflict-free ldmatrix  */
/* ================================================================== */
#define GEMM_K   1024
#define BK       32
#define NCH      (GEMM_K / BK)      /* 32 */
#define ROWB     80                 /* bytes per smem row */
#define TILE_B   (128 * ROWB)       /* 10240 */
#define STAGE_B  (4 * TILE_B)       /* 40960: AH, AL, BH, BL */
#define GEMM_SMEM (2 * STAGE_B)     /* 81920 */

__global__ __launch_bounds__(256)
void bf16_mma_gemm(const __nv_bfloat16* __restrict__ Ahi,
                   const __nv_bfloat16* __restrict__ Alo,
                   const __nv_bfloat16* __restrict__ Bhi,
                   const __nv_bfloat16* __restrict__ Blo,
                   const float* __restrict__ bias,
                   float* __restrict__ C)
{
    extern __shared__ char sm_raw[];
    const uint32_t sb = smem_u32(sm_raw);

    const int tid  = threadIdx.x;
    const int wid  = tid >> 5;
    const int lane = tid & 31;
    const int n0   = blockIdx.x * 128;
    const int m0   = blockIdx.y * 128;
    const int wm0  = (wid >> 2) * 64;   /* warp m offset in tile */
    const int wn0  = (wid & 3) * 32;    /* warp n offset in tile */

    float acc[4][4][4];
#pragma unroll
    for (int mt = 0; mt < 4; mt++)
#pragma unroll
        for (int nt = 0; nt < 4; nt++)
#pragma unroll
            for (int r = 0; r < 4; r++) acc[mt][nt][r] = 0.0f;

    /* --- async stage loader: 512 16B chunks per tile, 2/thread --- */
    auto load_stage = [&](int ch, int s) {
        const int k0 = ch * BK;
        const uint32_t st = sb + s * STAGE_B;
#pragma unroll
        for (int i = 0; i < 2; i++) {
            int idx = tid + i * 256;          /* 0..511 */
            int row = idx >> 2;
            int c16 = idx & 3;
            uint32_t so = (uint32_t)row * ROWB + c16 * 16;
            size_t gA = (size_t)(m0 + row) * GEMM_K + k0 + c16 * 8;
            size_t gB = (size_t)(n0 + row) * GEMM_K + k0 + c16 * 8;
            CP_ASYNC16(st + 0 * TILE_B + so, Ahi + gA);
            CP_ASYNC16(st + 1 * TILE_B + so, Alo + gA);
            CP_ASYNC16(st + 2 * TILE_B + so, Bhi + gB);
            CP_ASYNC16(st + 3 * TILE_B + so, Blo + gB);
        }
        CP_COMMIT();
    };

    load_stage(0, 0);

    for (int ch = 0; ch < NCH; ch++) {
        if (ch + 1 < NCH) { load_stage(ch + 1, (ch + 1) & 1); CP_WAIT(1); }
        else              { CP_WAIT(0); }
        __syncthreads();

        const uint32_t st = sb + (ch & 1) * STAGE_B;
        const uint32_t aH = st + 0 * TILE_B;
        const uint32_t aL = st + 1 * TILE_B;
        const uint32_t bH = st + 2 * TILE_B;
        const uint32_t bL = st + 3 * TILE_B;

        /* ldmatrix lane-address components */
        const int arow = wm0 + (lane & 15);           /* + mt*16 */
        const int acb  = (lane >> 4) * 16;            /* + ks*32 */
        const int brow = wn0 + ((lane & 16) >> 1) + (lane & 7); /* + np*16 */
        const int bcb  = (lane & 8) ? 16 : 0;         /* + ks*32 */

#pragma unroll
        for (int ks = 0; ks < 2; ks++) {
            uint32_t ah[4][4], al[4][4];
#pragma unroll
            for (int mt = 0; mt < 4; mt++) {
                uint32_t off = (uint32_t)(arow + mt * 16) * ROWB + ks * 32 + acb;
                LDM4(ah[mt], aH + off);
                LDM4(al[mt], aL + off);
            }
            uint32_t bh[4][2], bl[4][2];
#pragma unroll
            for (int np = 0; np < 2; np++) {
                uint32_t off = (uint32_t)(brow + np * 16) * ROWB + ks * 32 + bcb;
                uint32_t r[4];
                LDM4(r, bH + off);
                bh[2 * np][0] = r[0]; bh[2 * np][1] = r[1];
                bh[2 * np + 1][0] = r[2]; bh[2 * np + 1][1] = r[3];
                LDM4(r, bL + off);
                bl[2 * np][0] = r[0]; bl[2 * np][1] = r[1];
                bl[2 * np + 1][0] = r[2]; bl[2 * np + 1][1] = r[3];
            }
#pragma unroll
            for (int mt = 0; mt < 4; mt++)
#pragma unroll
                for (int nt = 0; nt < 4; nt++) {
                    MMA16816(acc[mt][nt], ah[mt], bh[nt][0], bh[nt][1]);
                    MMA16816(acc[mt][nt], ah[mt], bl[nt][0], bl[nt][1]);
                    MMA16816(acc[mt][nt], al[mt], bh[nt][0], bh[nt][1]);
                }
        }
        __syncthreads();
    }

    /* epilogue: bias + store (d frag: c0c1 row l/4, c2c3 row+8; col 2*(l%4)) */
#pragma unroll
    for (int mt = 0; mt < 4; mt++) {
        const int r0 = m0 + wm0 + mt * 16 + (lane >> 2);
#pragma unroll
        for (int nt = 0; nt < 4; nt++) {
            const int cc = n0 + wn0 + nt * 8 + (lane & 3) * 2;
            float2 b2 = *(const float2*)(bias + cc);
            float2 o0, o1;
            o0.x = acc[mt][nt][0] + b2.x; o0.y = acc[mt][nt][1] + b2.y;
            o1.x = acc[mt][nt][2] + b2.x; o1.y = acc[mt][nt][3] + b2.y;
            *(float2*)(C + (size_t)r0 * D_MODEL + cc)       = o0;
            *(float2*)(C + (size_t)(r0 + 8) * D_MODEL + cc) = o1;
        }
    }
}

/* ================================================================== */
/* Flash attention (fp32, online softmax) — unchanged                  */
/* ================================================================== */
#define PAD 68
#define ATT_SMEM_BYTES ((128 * PAD + 64 * PAD + 64 * PAD + 128 * PAD) * 4)

__global__ __launch_bounds__(256)
void attn_kernel()
{
    extern __shared__ float sm[];
    float* Qs = sm;
    float* Ks = Qs + 128 * PAD;
    float* Vs = Ks + 64 * PAD;
    float* Ps = Vs + 64 * PAD;

    const int tid = threadIdx.x;
    const int bh  = blockIdx.y;
    const int b   = bh >> 4;
    const int h   = bh & 15;
    const int q0  = blockIdx.x * 128;
    const int ty  = tid >> 4;
    const int tx  = tid & 15;
    const int r0  = ty * 8;
    const int c0  = tx * 4;

    const size_t bse = (size_t)b * SEQ * D_MODEL + (size_t)h * D_HEAD;
    const float* Qg = g_Q + bse;
    const float* Kg = g_K + bse;
    const float* Vg = g_V + bse;

#pragma unroll
    for (int i = 0; i < 8; i++) {
        int f4  = tid + i * 256;
        int row = f4 >> 4;
        int c4  = (f4 & 15) * 4;
        *(float4*)&Qs[row * PAD + c4] =
            *(const float4*)(Qg + (size_t)(q0 + row) * D_MODEL + c4);
    }

    float m_i[8], l_i[8], acc[8][4];
#pragma unroll
    for (int i = 0; i < 8; i++) {
        m_i[i] = -1e30f;
        l_i[i] = 0.0f;
#pragma unroll
        for (int j = 0; j < 4; j++) acc[i][j] = 0.0f;
    }

    for (int kt = 0; kt < SEQ; kt += 64) {
        __syncthreads();
#pragma unroll
        for (int i = 0; i < 4; i++) {
            int f4  = tid + i * 256;
            int row = f4 >> 4;
            int c4  = (f4 & 15) * 4;
            *(float4*)&Ks[row * PAD + c4] =
                *(const float4*)(Kg + (size_t)(kt + row) * D_MODEL + c4);
            *(float4*)&Vs[row * PAD + c4] =
                *(const float4*)(Vg + (size_t)(kt + row) * D_MODEL + c4);
        }
        __syncthreads();

        float sc[8][4];
#pragma unroll
        for (int i = 0; i < 8; i++)
#pragma unroll
            for (int j = 0; j < 4; j++) sc[i][j] = 0.0f;

        for (int k4 = 0; k4 < 64; k4 += 4) {
            float4 kv[4];
#pragma unroll
            for (int j = 0; j < 4; j++)
                kv[j] = *(const float4*)&Ks[(c0 + j) * PAD + k4];
#pragma unroll
            for (int i = 0; i < 8; i++) {
                float4 qv = *(const float4*)&Qs[(r0 + i) * PAD + k4];
#pragma unroll
                for (int j = 0; j < 4; j++) {
                    sc[i][j] += qv.x * kv[j].x;
                    sc[i][j] += qv.y * kv[j].y;
                    sc[i][j] += qv.z * kv[j].z;
                    sc[i][j] += qv.w * kv[j].w;
                }
            }
        }

#pragma unroll
        for (int i = 0; i < 8; i++) {
            float mt = -1e30f;
#pragma unroll
            for (int j = 0; j < 4; j++) {
                sc[i][j] *= ATT_SCALE;
                mt = fmaxf(mt, sc[i][j]);
            }
#pragma unroll
            for (int off = 8; off > 0; off >>= 1)
                mt = fmaxf(mt, __shfl_xor_sync(0xffffffffu, mt, off));
            float mnew = fmaxf(m_i[i], mt);
            float corr = __expf(m_i[i] - mnew);
            float rs = 0.0f;
#pragma unroll
            for (int j = 0; j < 4; j++) {
                float p = __expf(sc[i][j] - mnew);
                Ps[(r0 + i) * PAD + c0 + j] = p;
                rs += p;
            }
#pragma unroll
            for (int off = 8; off > 0; off >>= 1)
                rs += __shfl_xor_sync(0xffffffffu, rs, off);
            l_i[i] = l_i[i] * corr + rs;
            m_i[i] = mnew;
#pragma unroll
            for (int j = 0; j < 4; j++) acc[i][j] *= corr;
        }
        __syncwarp();

        for (int kk4 = 0; kk4 < 64; kk4 += 4) {
            float4 vv[4];
#pragma unroll
            for (int q = 0; q < 4; q++)
                vv[q] = *(const float4*)&Vs[(kk4 + q) * PAD + c0];
#pragma unroll
            for (int i = 0; i < 8; i++) {
                float4 pv = *(const float4*)&Ps[(r0 + i) * PAD + kk4];
                acc[i][0] += pv.x * vv[0].x + pv.y * vv[1].x + pv.z * vv[2].x + pv.w * vv[3].x;
                acc[i][1] += pv.x * vv[0].y + pv.y * vv[1].y + pv.z * vv[2].y + pv.w * vv[3].y;
                acc[i][2] += pv.x * vv[0].z + pv.y * vv[1].z + pv.z * vv[2].z + pv.w * vv[3].z;
                acc[i][3] += pv.x * vv[0].w + pv.y * vv[1].w + pv.z * vv[2].w + pv.w * vv[3].w;
            }
        }
    }

    float* Og = g_O + bse;
#pragma unroll
    for (int i = 0; i < 8; i++) {
        float inv = 1.0f / l_i[i];
        float4 o;
        o.x = acc[i][0] * inv;
        o.y = acc[i][1] * inv;
        o.z = acc[i][2] * inv;
        o.w = acc[i][3] * inv;
        *(float4*)(Og + (size_t)(q0 + r0 + i) * D_MODEL + c0) = o;
    }
}

/* ================================================================== */
/* launch                                                              */
/* ================================================================== */
extern "C" void kernel_launch(void* const* d_in, const int* in_sizes, int n_in,
                              void* d_out, int out_size)
{
    const float* x  = (const float*)d_in[0];
    const float* Wq = (const float*)d_in[1];
    const float* bq = (const float*)d_in[2];
    const float* Wk = (const float*)d_in[3];
    const float* bk = (const float*)d_in[4];
    const float* Wv = (const float*)d_in[5];
    const float* bv = (const float*)d_in[6];
    const float* Wo = (const float*)d_in[7];
    const float* bo = (const float*)d_in[8];
    float* out = (float*)d_out;

    float *q, *k, *v, *o;
    __nv_bfloat16 *xh, *xl, *wh, *wl;
    cudaGetSymbolAddress((void**)&q,  g_Q);
    cudaGetSymbolAddress((void**)&k,  g_K);
    cudaGetSymbolAddress((void**)&v,  g_V);
    cudaGetSymbolAddress((void**)&o,  g_O);
    cudaGetSymbolAddress((void**)&xh, g_Xhi);
    cudaGetSymbolAddress((void**)&xl, g_Xlo);
    cudaGetSymbolAddress((void**)&wh, g_Whi);
    cudaGetSymbolAddress((void**)&wl, g_Wlo);

    cudaFuncSetAttribute(attn_kernel,
                         cudaFuncAttributeMaxDynamicSharedMemorySize, ATT_SMEM_BYTES);
    cudaFuncSetAttribute(bf16_mma_gemm,
                         cudaFuncAttributeMaxDynamicSharedMemorySize, GEMM_SMEM);

    const int XN4 = (MROWS * D_MODEL) / 4;
    const int WN4 = (D_MODEL * D_MODEL) / 4;
    const size_t WOFF = (size_t)D_MODEL * D_MODEL;

    cvt_split_kernel<<<(XN4 + 255) / 256, 256>>>(
        (const float4*)x, (__nv_bfloat162*)xh, (__nv_bfloat162*)xl, XN4);
    const float* Ws[4] = {Wq, Wk, Wv, Wo};
    for (int i = 0; i < 4; i++)
        cvt_split_kernel<<<(WN4 + 255) / 256, 256>>>(
            (const float4*)Ws[i],
            (__nv_bfloat162*)(wh + i * WOFF),
            (__nv_bfloat162*)(wl + i * WOFF), WN4);

    dim3 gg(D_MODEL / 128, MROWS / 128);   /* (8, 64) */
    bf16_mma_gemm<<<gg, 256, GEMM_SMEM>>>(xh, xl, wh + 0 * WOFF, wl + 0 * WOFF, bq, q);
    bf16_mma_gemm<<<gg, 256, GEMM_SMEM>>>(xh, xl, wh + 1 * WOFF, wl + 1 * WOFF, bk, k);
    bf16_mma_gemm<<<gg, 256, GEMM_SMEM>>>(xh, xl, wh + 2 * WOFF, wl + 2 * WOFF, bv, v);

    dim3 ag(SEQ / 128, BATCH * NUM_HEADS); /* (16, 64) */
    attn_kernel<<<ag, 256, ATT_SMEM_BYTES>>>();

    cvt_split_kernel<<<(XN4 + 255) / 256, 256>>>(
        (const float4*)o, (__nv_bfloat162*)xh, (__nv_bfloat162*)xl, XN4);
    bf16_mma_gemm<<<gg, 256, GEMM_SMEM>>>(xh, xl, wh + 3 * WOFF, wl + 3 * WOFF, bo, out);
}